// round 1
// baseline (speedup 1.0000x reference)
#include <cuda_runtime.h>
#include <math.h>

#define B_ 16
#define N_ 2048
#define D_ 64
#define NEG_INF_ (-1e9f)

// ---------------- scratch (device globals; no allocation allowed) ----------
__device__ float g_qT[(size_t)B_ * D_ * N_];   // [B][D][N] transposed q
__device__ float g_kT[(size_t)B_ * D_ * N_];   // [B][D][N] transposed k
__device__ float g_v [(size_t)B_ * N_ * D_];   // [B][N][D]
__device__ float g_ctx[(size_t)B_ * N_ * D_];  // [B][N][D]

// ============================================================================
// Kernel 1: q = x@Wq+bq, k = x@Wk+bk (stored transposed), v = x@Wv+bv
// grid (32, 16) : 64 rows per block, 256 threads
// ============================================================================
__global__ __launch_bounds__(256) void proj_qkv(
    const float* __restrict__ x,
    const float* __restrict__ Wq, const float* __restrict__ bq,
    const float* __restrict__ Wk, const float* __restrict__ bk,
    const float* __restrict__ Wv, const float* __restrict__ bv)
{
    __shared__ float xs[64][65];   // pad 65: conflict-free for n-fast reads
    __shared__ float Ws[64][64];
    __shared__ float bs[64];

    const int tid = threadIdx.x;
    const int b   = blockIdx.y;
    const int n0  = blockIdx.x * 64;

    // load x tile (coalesced, d-fast)
    for (int it = 0; it < 16; ++it) {
        int idx = tid + it * 256;          // 0..4095
        int n = idx >> 6, d = idx & 63;
        xs[n][d] = x[((size_t)(b * N_ + n0 + n)) * D_ + d];
    }

    for (int mat = 0; mat < 3; ++mat) {
        const float* W = (mat == 0) ? Wq : (mat == 1) ? Wk : Wv;
        const float* bb = (mat == 0) ? bq : (mat == 1) ? bk : bv;
        __syncthreads();   // previous mat done reading Ws / xs visible
        for (int it = 0; it < 16; ++it) {
            int idx = tid + it * 256;
            Ws[idx >> 6][idx & 63] = W[idx];
        }
        if (tid < 64) bs[tid] = bb[tid];
        __syncthreads();

        if (mat < 2) {
            // n-fast mapping -> coalesced transposed store
            float* dst = (mat == 0) ? g_qT : g_kT;
            for (int it = 0; it < 16; ++it) {
                int idx = tid + it * 256;
                int n = idx & 63, d = idx >> 6;
                float acc = bs[d];
                #pragma unroll
                for (int dd = 0; dd < 64; ++dd) acc += xs[n][dd] * Ws[dd][d];
                dst[((size_t)(b * D_ + d)) * N_ + n0 + n] = acc;
            }
        } else {
            // d-fast mapping -> coalesced normal store
            for (int it = 0; it < 16; ++it) {
                int idx = tid + it * 256;
                int d = idx & 63, n = idx >> 6;
                float acc = bs[d];
                #pragma unroll
                for (int dd = 0; dd < 64; ++dd) acc += xs[n][dd] * Ws[dd][d];
                g_v[((size_t)(b * N_ + n0 + n)) * D_ + d] = acc;
            }
        }
    }
}

// ============================================================================
// Kernel 2: masked attention.
// grid (16, 16): block = (batch b, 128 query rows), 256 threads.
// Phase 1: scores tiles (128x128), mask, write scaled scores to attn (scratch),
//          exact online row max/sum.
// Phase 2: re-read scores, write normalized p to attn, accumulate ctx = p @ v.
// ============================================================================
#define SPQ 136   // qs/ks smem row stride (floats)
#define SPP 132   // ps smem row stride
#define SPV 68    // vs smem row stride
#define SMEM2_BYTES 102400

__global__ void __launch_bounds__(256, 2) attn_kernel(
    const int* __restrict__ adj, float* __restrict__ attn)
{
    extern __shared__ float smem2[];
    float* qs = smem2;                 // [64][SPQ]   phase 1
    float* ks = smem2 + 64 * SPQ;      // [64][SPQ]   phase 1
    float* ps = smem2;                 // [128][SPP]  phase 2 (overlaps qs/ks)
    float* vs = smem2 + 128 * SPP;     // [128][SPV]  phase 2

    const int tid = threadIdx.x;
    const int tx = tid & 15, ty = tid >> 4;      // 16x16 threads, 8x8 regs each
    const int b  = blockIdx.y;
    const int r0 = blockIdx.x * 128;

    // ---- load q tile (transposed layout, coalesced) ----
    for (int it = 0; it < 8; ++it) {
        int idx4 = tid + it * 256;               // 0..2047 float4s
        int r4 = idx4 & 31, d = idx4 >> 5;
        *(float4*)&qs[d * SPQ + r4 * 4] =
            *(const float4*)&g_qT[((size_t)(b * D_ + d)) * N_ + r0 + r4 * 4];
    }

    float runM[8], runL[8];
    #pragma unroll
    for (int i = 0; i < 8; ++i) { runM[i] = -INFINITY; runL[i] = 0.f; }

    // =================== Phase 1 ===================
    for (int mt = 0; mt < N_ / 128; ++mt) {
        const int m0 = mt * 128;
        __syncthreads();
        for (int it = 0; it < 8; ++it) {
            int idx4 = tid + it * 256;
            int r4 = idx4 & 31, d = idx4 >> 5;
            *(float4*)&ks[d * SPQ + r4 * 4] =
                *(const float4*)&g_kT[((size_t)(b * D_ + d)) * N_ + m0 + r4 * 4];
        }
        __syncthreads();

        float acc[8][8];
        #pragma unroll
        for (int i = 0; i < 8; ++i)
            #pragma unroll
            for (int j = 0; j < 8; ++j) acc[i][j] = 0.f;

        #pragma unroll 8
        for (int d = 0; d < 64; ++d) {
            float a[8], bb[8];
            *(float4*)&a[0]  = *(float4*)&qs[d * SPQ + ty * 8];
            *(float4*)&a[4]  = *(float4*)&qs[d * SPQ + ty * 8 + 4];
            *(float4*)&bb[0] = *(float4*)&ks[d * SPQ + tx * 8];
            *(float4*)&bb[4] = *(float4*)&ks[d * SPQ + tx * 8 + 4];
            #pragma unroll
            for (int i = 0; i < 8; ++i)
                #pragma unroll
                for (int j = 0; j < 8; ++j) acc[i][j] += a[i] * bb[j];
        }

        // mask + scale + store scores + online stats
        #pragma unroll
        for (int i = 0; i < 8; ++i) {
            size_t base = ((size_t)(b * N_ + r0 + ty * 8 + i)) * N_ + m0 + tx * 8;
            int4 A0 = *(const int4*)&adj[base];
            int4 A1 = *(const int4*)&adj[base + 4];
            float s[8];
            s[0] = (A0.x > 0) ? acc[i][0] * 0.125f : NEG_INF_;
            s[1] = (A0.y > 0) ? acc[i][1] * 0.125f : NEG_INF_;
            s[2] = (A0.z > 0) ? acc[i][2] * 0.125f : NEG_INF_;
            s[3] = (A0.w > 0) ? acc[i][3] * 0.125f : NEG_INF_;
            s[4] = (A1.x > 0) ? acc[i][4] * 0.125f : NEG_INF_;
            s[5] = (A1.y > 0) ? acc[i][5] * 0.125f : NEG_INF_;
            s[6] = (A1.z > 0) ? acc[i][6] * 0.125f : NEG_INF_;
            s[7] = (A1.w > 0) ? acc[i][7] * 0.125f : NEG_INF_;
            *(float4*)&attn[base]     = make_float4(s[0], s[1], s[2], s[3]);
            *(float4*)&attn[base + 4] = make_float4(s[4], s[5], s[6], s[7]);

            float tm = s[0];
            #pragma unroll
            for (int j = 1; j < 8; ++j) tm = fmaxf(tm, s[j]);
            tm = fmaxf(tm, __shfl_xor_sync(0xffffffffu, tm, 1));
            tm = fmaxf(tm, __shfl_xor_sync(0xffffffffu, tm, 2));
            tm = fmaxf(tm, __shfl_xor_sync(0xffffffffu, tm, 4));
            tm = fmaxf(tm, __shfl_xor_sync(0xffffffffu, tm, 8));
            float nm = fmaxf(runM[i], tm);
            float ls = 0.f;
            #pragma unroll
            for (int j = 0; j < 8; ++j) ls += __expf(s[j] - nm);
            ls += __shfl_xor_sync(0xffffffffu, ls, 1);
            ls += __shfl_xor_sync(0xffffffffu, ls, 2);
            ls += __shfl_xor_sync(0xffffffffu, ls, 4);
            ls += __shfl_xor_sync(0xffffffffu, ls, 8);
            runL[i] = runL[i] * __expf(runM[i] - nm) + ls;
            runM[i] = nm;
        }
    }

    float invL[8];
    #pragma unroll
    for (int i = 0; i < 8; ++i) invL[i] = 1.f / runL[i];

    // =================== Phase 2 ===================
    const int rg = tid & 15;      // rows rg + 16k, k = 0..7
    const int dg = tid >> 4;      // d cols dg*4 .. dg*4+3
    float ctx[8][4];
    #pragma unroll
    for (int k = 0; k < 8; ++k)
        #pragma unroll
        for (int c = 0; c < 4; ++c) ctx[k][c] = 0.f;

    for (int mt = 0; mt < N_ / 128; ++mt) {
        const int m0 = mt * 128;
        __syncthreads();   // previous GEMM done before ps/vs rewrite

        // load v tile
        for (int it = 0; it < 8; ++it) {
            int idx4 = tid + it * 256;
            int d4 = idx4 & 15, m = idx4 >> 4;
            *(float4*)&vs[m * SPV + d4 * 4] =
                *(const float4*)&g_v[((size_t)(b * N_ + m0 + m)) * D_ + d4 * 4];
        }

        // re-read scores, normalize, write final attn + stage in smem
        #pragma unroll
        for (int i = 0; i < 8; ++i) {
            int r = ty * 8 + i;
            size_t base = ((size_t)(b * N_ + r0 + r)) * N_ + m0 + tx * 8;
            float4 s0 = *(const float4*)&attn[base];
            float4 s1 = *(const float4*)&attn[base + 4];
            float4 p0, p1;
            p0.x = __expf(s0.x - runM[i]) * invL[i];
            p0.y = __expf(s0.y - runM[i]) * invL[i];
            p0.z = __expf(s0.z - runM[i]) * invL[i];
            p0.w = __expf(s0.w - runM[i]) * invL[i];
            p1.x = __expf(s1.x - runM[i]) * invL[i];
            p1.y = __expf(s1.y - runM[i]) * invL[i];
            p1.z = __expf(s1.z - runM[i]) * invL[i];
            p1.w = __expf(s1.w - runM[i]) * invL[i];
            *(float4*)&attn[base]     = p0;
            *(float4*)&attn[base + 4] = p1;
            *(float4*)&ps[r * SPP + tx * 8]     = p0;
            *(float4*)&ps[r * SPP + tx * 8 + 4] = p1;
        }
        __syncthreads();

        // ctx += p @ v
        #pragma unroll 4
        for (int m4 = 0; m4 < 32; ++m4) {
            float vrow[4][4];
            #pragma unroll
            for (int r = 0; r < 4; ++r)
                *(float4*)vrow[r] = *(float4*)&vs[(m4 * 4 + r) * SPV + dg * 4];
            #pragma unroll
            for (int k = 0; k < 8; ++k) {
                float p4[4];
                *(float4*)p4 = *(float4*)&ps[(rg + 16 * k) * SPP + m4 * 4];
                #pragma unroll
                for (int r = 0; r < 4; ++r)
                    #pragma unroll
                    for (int c = 0; c < 4; ++c)
                        ctx[k][c] += p4[r] * vrow[r][c];
            }
        }
    }

    #pragma unroll
    for (int k = 0; k < 8; ++k)
        *(float4*)&g_ctx[((size_t)(b * N_ + r0 + rg + 16 * k)) * D_ + dg * 4] =
            make_float4(ctx[k][0], ctx[k][1], ctx[k][2], ctx[k][3]);
}

// ============================================================================
// Kernel 3: ctx2 = ctx@Wo+bo ; y = relu(x@Wl[0:64] + ctx2@Wl[64:128] + bl)
// grid (32, 16): 64 rows per block, 256 threads. Each thread: fixed d, 16 rows.
// ============================================================================
__global__ __launch_bounds__(256) void out_proj(
    const float* __restrict__ x,
    const float* __restrict__ Wo, const float* __restrict__ bo,
    const float* __restrict__ Wl, const float* __restrict__ bl,
    float* __restrict__ y)
{
    __shared__ float buf[64][64];   // ctx tile, then x tile
    __shared__ float c2s[64][64];
    __shared__ float Ws[64][64];

    const int tid = threadIdx.x;
    const int b = blockIdx.y, n0 = blockIdx.x * 64;
    const int d = tid & 63;

    for (int it = 0; it < 16; ++it) {
        int idx = tid + it * 256;
        int n = idx >> 6, dd = idx & 63;
        buf[n][dd] = g_ctx[((size_t)(b * N_ + n0 + n)) * D_ + dd];
        Ws[n][dd]  = Wo[idx];
    }
    __syncthreads();

    const float boD = bo[d];
    float c2loc[16];
    for (int it = 0; it < 16; ++it) {
        int n = (tid >> 6) + it * 4;
        float acc = boD;
        #pragma unroll
        for (int dd = 0; dd < 64; ++dd) acc += buf[n][dd] * Ws[dd][d];
        c2loc[it] = acc;
    }
    __syncthreads();   // all reads of buf/Ws done

    for (int it = 0; it < 16; ++it) {
        int n = (tid >> 6) + it * 4;
        c2s[n][d] = c2loc[it];
    }
    for (int it = 0; it < 16; ++it) {
        int idx = tid + it * 256;
        int n = idx >> 6, dd = idx & 63;
        buf[n][dd] = x[((size_t)(b * N_ + n0 + n)) * D_ + dd];
        Ws[n][dd]  = Wl[idx];          // Wl top half (rows 0..63)
    }
    __syncthreads();

    const float blD = bl[d];
    float yl[16];
    for (int it = 0; it < 16; ++it) {
        int n = (tid >> 6) + it * 4;
        float acc = blD;
        #pragma unroll
        for (int dd = 0; dd < 64; ++dd) acc += buf[n][dd] * Ws[dd][d];
        yl[it] = acc;
    }
    __syncthreads();

    for (int it = 0; it < 16; ++it) {
        int idx = tid + it * 256;
        Ws[idx >> 6][idx & 63] = Wl[64 * 64 + idx];   // Wl bottom half
    }
    __syncthreads();

    for (int it = 0; it < 16; ++it) {
        int n = (tid >> 6) + it * 4;
        float acc = yl[it];
        #pragma unroll
        for (int dd = 0; dd < 64; ++dd) acc += c2s[n][dd] * Ws[dd][d];
        y[((size_t)(b * N_ + n0 + n)) * D_ + d] = fmaxf(acc, 0.f);
    }
}

// ============================================================================
extern "C" void kernel_launch(void* const* d_in, const int* in_sizes, int n_in,
                              void* d_out, int out_size)
{
    const float* x   = (const float*)d_in[0];
    const int*   adj = (const int*)  d_in[1];
    const float* Wq  = (const float*)d_in[2];
    const float* bq  = (const float*)d_in[3];
    const float* Wk  = (const float*)d_in[4];
    const float* bk  = (const float*)d_in[5];
    const float* Wv  = (const float*)d_in[6];
    const float* bv  = (const float*)d_in[7];
    const float* Wo  = (const float*)d_in[8];
    const float* bo  = (const float*)d_in[9];
    const float* Wl  = (const float*)d_in[10];
    const float* bl  = (const float*)d_in[11];

    float* y    = (float*)d_out;                         // [B,N,D]
    float* attn = (float*)d_out + (size_t)B_ * N_ * D_;  // [B,N,N]

    cudaFuncSetAttribute(attn_kernel,
                         cudaFuncAttributeMaxDynamicSharedMemorySize,
                         SMEM2_BYTES);

    proj_qkv<<<dim3(32, 16), 256>>>(x, Wq, bq, Wk, bk, Wv, bv);
    attn_kernel<<<dim3(16, 16), 256, SMEM2_BYTES>>>(adj, attn);
    out_proj<<<dim3(32, 16), 256>>>(x, Wo, bo, Wl, bl, y);
}

// round 2
// speedup vs baseline: 1.0913x; 1.0913x over previous
#include <cuda_runtime.h>
#include <math.h>

#define B_ 16
#define N_ 2048
#define D_ 64
#define NEG_INF_ (-1e9f)

typedef unsigned long long u64;

__device__ __forceinline__ u64 bcast2(float v) {
    u64 r; asm("mov.b64 %0, {%1, %1};" : "=l"(r) : "f"(v)); return r;
}
__device__ __forceinline__ void fma2(u64& d, u64 a, u64 b) {
    asm("fma.rn.f32x2 %0, %1, %2, %0;" : "+l"(d) : "l"(a), "l"(b));
}
__device__ __forceinline__ float2 unpack2(u64 v) {
    float2 f; asm("mov.b64 {%0, %1}, %2;" : "=f"(f.x), "=f"(f.y) : "l"(v)); return f;
}

// ---------------- scratch (device globals; no allocation allowed) ----------
__device__ float g_qT[(size_t)B_ * D_ * N_];   // [B][D][N] transposed q
__device__ float g_kT[(size_t)B_ * D_ * N_];   // [B][D][N] transposed k
__device__ float g_v [(size_t)B_ * N_ * D_];   // [B][N][D]
__device__ float g_ctx[(size_t)B_ * N_ * D_];  // [B][N][D]

// ============================================================================
// Kernel 1: q = x@Wq+bq (T), k = x@Wk+bk (T), v = x@Wv+bv
// grid (16, 16): 128 rows per block, 256 threads.
// xsT[d][n] in smem -> conflict-free float4 loads of 4 consecutive n.
// Each thread: 4 n x 8 d register tile, fma.rn.f32x2.
// ============================================================================
#define PROJ_SMEM_BYTES ((64 * 132 + 64 * 64 + 64) * 4)

__global__ __launch_bounds__(256) void proj_qkv(
    const float* __restrict__ x,
    const float* __restrict__ Wq, const float* __restrict__ bq,
    const float* __restrict__ Wk, const float* __restrict__ bk,
    const float* __restrict__ Wv, const float* __restrict__ bv)
{
    extern __shared__ float psm[];
    float* xsT = psm;               // [64][132]  (d-major, n fast)
    float* Ws  = psm + 64 * 132;    // [64][64]
    float* bs  = Ws + 64 * 64;

    const int tid = threadIdx.x;
    const int b   = blockIdx.y;
    const int n0  = blockIdx.x * 128;

    // load x tile transposed into smem
    for (int it = 0; it < 8; ++it) {
        int idx4 = tid + it * 256;          // 0..2047
        int d4 = idx4 >> 7, n = idx4 & 127;
        float4 v = *(const float4*)&x[((size_t)(b * N_ + n0 + n)) * D_ + d4 * 4];
        xsT[(d4 * 4 + 0) * 132 + n] = v.x;
        xsT[(d4 * 4 + 1) * 132 + n] = v.y;
        xsT[(d4 * 4 + 2) * 132 + n] = v.z;
        xsT[(d4 * 4 + 3) * 132 + n] = v.w;
    }

    const int nlo  = (tid & 31) * 4;   // 4 consecutive rows
    const int dblk = (tid >> 5) * 8;   // 8 output cols

    for (int mat = 0; mat < 3; ++mat) {
        const float* W  = (mat == 0) ? Wq : (mat == 1) ? Wk : Wv;
        const float* bb = (mat == 0) ? bq : (mat == 1) ? bk : bv;
        __syncthreads();   // previous mat done with Ws; xsT visible
        for (int it = 0; it < 16; ++it) {
            int idx = tid + it * 256;
            Ws[idx] = W[idx];
        }
        if (tid < 64) bs[tid] = bb[tid];
        __syncthreads();

        u64 acc[4][4];
        #pragma unroll
        for (int i = 0; i < 4; ++i)
            #pragma unroll
            for (int jp = 0; jp < 4; ++jp) acc[i][jp] = 0ull;

        #pragma unroll 4
        for (int dd = 0; dd < 64; ++dd) {
            float4 a4 = *(float4*)&xsT[dd * 132 + nlo];
            ulonglong2 w0 = *(ulonglong2*)&Ws[dd * 64 + dblk];
            ulonglong2 w1 = *(ulonglong2*)&Ws[dd * 64 + dblk + 4];
            float av[4] = {a4.x, a4.y, a4.z, a4.w};
            #pragma unroll
            for (int i = 0; i < 4; ++i) {
                u64 ab = bcast2(av[i]);
                fma2(acc[i][0], ab, w0.x);
                fma2(acc[i][1], ab, w0.y);
                fma2(acc[i][2], ab, w1.x);
                fma2(acc[i][3], ab, w1.y);
            }
        }

        float f[4][8];
        #pragma unroll
        for (int i = 0; i < 4; ++i)
            #pragma unroll
            for (int jp = 0; jp < 4; ++jp) {
                float2 u = unpack2(acc[i][jp]);
                f[i][jp * 2]     = u.x + bs[dblk + jp * 2];
                f[i][jp * 2 + 1] = u.y + bs[dblk + jp * 2 + 1];
            }

        if (mat < 2) {
            float* dst = (mat == 0) ? g_qT : g_kT;
            #pragma unroll
            for (int j = 0; j < 8; ++j) {
                *(float4*)&dst[((size_t)(b * D_ + dblk + j)) * N_ + n0 + nlo] =
                    make_float4(f[0][j], f[1][j], f[2][j], f[3][j]);
            }
        } else {
            #pragma unroll
            for (int i = 0; i < 4; ++i) {
                size_t o = ((size_t)(b * N_ + n0 + nlo + i)) * D_ + dblk;
                *(float4*)&g_v[o]     = make_float4(f[i][0], f[i][1], f[i][2], f[i][3]);
                *(float4*)&g_v[o + 4] = make_float4(f[i][4], f[i][5], f[i][6], f[i][7]);
            }
        }
    }
}

// ============================================================================
// Kernel 2: masked attention with fma.rn.f32x2 GEMMs.
// grid (16, 16): block = (batch b, 128 query rows), 256 threads.
// ============================================================================
#define SPQ 136   // qs/ks smem row stride (floats)
#define SPP 132   // ps smem row stride
#define SPV 68    // vs smem row stride
#define SMEM2_BYTES 102400

__global__ void __launch_bounds__(256, 2) attn_kernel(
    const int* __restrict__ adj, float* __restrict__ attn)
{
    extern __shared__ float smem2[];
    float* qs = smem2;                 // [64][SPQ]   phase 1
    float* ks = smem2 + 64 * SPQ;      // [64][SPQ]   phase 1
    float* ps = smem2;                 // [128][SPP]  phase 2 (overlaps qs/ks)
    float* vs = smem2 + 128 * SPP;     // [128][SPV]  phase 2

    const int tid = threadIdx.x;
    const int tx = tid & 15, ty = tid >> 4;      // 16x16 threads, 8x8 regs each
    const int b  = blockIdx.y;
    const int r0 = blockIdx.x * 128;

    // ---- load q tile (transposed layout, coalesced) ----
    for (int it = 0; it < 8; ++it) {
        int idx4 = tid + it * 256;               // 0..2047 float4s
        int r4 = idx4 & 31, d = idx4 >> 5;
        *(float4*)&qs[d * SPQ + r4 * 4] =
            *(const float4*)&g_qT[((size_t)(b * D_ + d)) * N_ + r0 + r4 * 4];
    }

    float runM[8], runL[8];
    #pragma unroll
    for (int i = 0; i < 8; ++i) { runM[i] = -INFINITY; runL[i] = 0.f; }

    // =================== Phase 1: scores + mask + online stats ==============
    for (int mt = 0; mt < N_ / 128; ++mt) {
        const int m0 = mt * 128;
        __syncthreads();
        for (int it = 0; it < 8; ++it) {
            int idx4 = tid + it * 256;
            int r4 = idx4 & 31, d = idx4 >> 5;
            *(float4*)&ks[d * SPQ + r4 * 4] =
                *(const float4*)&g_kT[((size_t)(b * D_ + d)) * N_ + m0 + r4 * 4];
        }
        __syncthreads();

        u64 accp[8][4];
        #pragma unroll
        for (int i = 0; i < 8; ++i)
            #pragma unroll
            for (int jp = 0; jp < 4; ++jp) accp[i][jp] = 0ull;

        #pragma unroll 4
        for (int d = 0; d < 64; ++d) {
            float4 a0 = *(float4*)&qs[d * SPQ + ty * 8];
            float4 a1 = *(float4*)&qs[d * SPQ + ty * 8 + 4];
            ulonglong2 k0 = *(ulonglong2*)&ks[d * SPQ + tx * 8];
            ulonglong2 k1 = *(ulonglong2*)&ks[d * SPQ + tx * 8 + 4];
            float av[8] = {a0.x, a0.y, a0.z, a0.w, a1.x, a1.y, a1.z, a1.w};
            #pragma unroll
            for (int i = 0; i < 8; ++i) {
                u64 ab = bcast2(av[i]);
                fma2(accp[i][0], ab, k0.x);
                fma2(accp[i][1], ab, k0.y);
                fma2(accp[i][2], ab, k1.x);
                fma2(accp[i][3], ab, k1.y);
            }
        }

        // mask + scale + store scores + online stats
        #pragma unroll
        for (int i = 0; i < 8; ++i) {
            size_t base = ((size_t)(b * N_ + r0 + ty * 8 + i)) * N_ + m0 + tx * 8;
            int4 A0 = *(const int4*)&adj[base];
            int4 A1 = *(const int4*)&adj[base + 4];
            float2 u0 = unpack2(accp[i][0]);
            float2 u1 = unpack2(accp[i][1]);
            float2 u2 = unpack2(accp[i][2]);
            float2 u3 = unpack2(accp[i][3]);
            float s[8];
            s[0] = (A0.x > 0) ? u0.x * 0.125f : NEG_INF_;
            s[1] = (A0.y > 0) ? u0.y * 0.125f : NEG_INF_;
            s[2] = (A0.z > 0) ? u1.x * 0.125f : NEG_INF_;
            s[3] = (A0.w > 0) ? u1.y * 0.125f : NEG_INF_;
            s[4] = (A1.x > 0) ? u2.x * 0.125f : NEG_INF_;
            s[5] = (A1.y > 0) ? u2.y * 0.125f : NEG_INF_;
            s[6] = (A1.z > 0) ? u3.x * 0.125f : NEG_INF_;
            s[7] = (A1.w > 0) ? u3.y * 0.125f : NEG_INF_;
            *(float4*)&attn[base]     = make_float4(s[0], s[1], s[2], s[3]);
            *(float4*)&attn[base + 4] = make_float4(s[4], s[5], s[6], s[7]);

            float tm = s[0];
            #pragma unroll
            for (int j = 1; j < 8; ++j) tm = fmaxf(tm, s[j]);
            tm = fmaxf(tm, __shfl_xor_sync(0xffffffffu, tm, 1));
            tm = fmaxf(tm, __shfl_xor_sync(0xffffffffu, tm, 2));
            tm = fmaxf(tm, __shfl_xor_sync(0xffffffffu, tm, 4));
            tm = fmaxf(tm, __shfl_xor_sync(0xffffffffu, tm, 8));
            float nm = fmaxf(runM[i], tm);
            float ls = 0.f;
            #pragma unroll
            for (int j = 0; j < 8; ++j) ls += __expf(s[j] - nm);
            ls += __shfl_xor_sync(0xffffffffu, ls, 1);
            ls += __shfl_xor_sync(0xffffffffu, ls, 2);
            ls += __shfl_xor_sync(0xffffffffu, ls, 4);
            ls += __shfl_xor_sync(0xffffffffu, ls, 8);
            runL[i] = runL[i] * __expf(runM[i] - nm) + ls;
            runM[i] = nm;
        }
    }

    float invL[8];
    #pragma unroll
    for (int i = 0; i < 8; ++i) invL[i] = 1.f / runL[i];

    // =================== Phase 2: normalize + ctx = p @ v ===================
    const int rg = tid & 31;      // rows rg + 32k, k = 0..3
    const int dg = tid >> 5;      // 8 cols dg*8 .. dg*8+7
    u64 ctxp[4][4];
    #pragma unroll
    for (int k = 0; k < 4; ++k)
        #pragma unroll
        for (int jp = 0; jp < 4; ++jp) ctxp[k][jp] = 0ull;

    for (int mt = 0; mt < N_ / 128; ++mt) {
        const int m0 = mt * 128;
        __syncthreads();   // previous GEMM done before ps/vs rewrite

        // load v tile
        for (int it = 0; it < 8; ++it) {
            int idx4 = tid + it * 256;
            int d4 = idx4 & 15, m = idx4 >> 4;
            *(float4*)&vs[m * SPV + d4 * 4] =
                *(const float4*)&g_v[((size_t)(b * N_ + m0 + m)) * D_ + d4 * 4];
        }

        // re-read scores, normalize, write final attn + stage in smem
        #pragma unroll
        for (int i = 0; i < 8; ++i) {
            int r = ty * 8 + i;
            size_t base = ((size_t)(b * N_ + r0 + r)) * N_ + m0 + tx * 8;
            float4 s0 = *(const float4*)&attn[base];
            float4 s1 = *(const float4*)&attn[base + 4];
            float4 p0, p1;
            p0.x = __expf(s0.x - runM[i]) * invL[i];
            p0.y = __expf(s0.y - runM[i]) * invL[i];
            p0.z = __expf(s0.z - runM[i]) * invL[i];
            p0.w = __expf(s0.w - runM[i]) * invL[i];
            p1.x = __expf(s1.x - runM[i]) * invL[i];
            p1.y = __expf(s1.y - runM[i]) * invL[i];
            p1.z = __expf(s1.z - runM[i]) * invL[i];
            p1.w = __expf(s1.w - runM[i]) * invL[i];
            *(float4*)&attn[base]     = p0;
            *(float4*)&attn[base + 4] = p1;
            *(float4*)&ps[r * SPP + tx * 8]     = p0;
            *(float4*)&ps[r * SPP + tx * 8 + 4] = p1;
        }
        __syncthreads();

        // ctx += p @ v   (f32x2)
        #pragma unroll 2
        for (int m4 = 0; m4 < 32; ++m4) {
            u64 vp[4][4];
            #pragma unroll
            for (int r = 0; r < 4; ++r) {
                ulonglong2 v0 = *(ulonglong2*)&vs[(m4 * 4 + r) * SPV + dg * 8];
                ulonglong2 v1 = *(ulonglong2*)&vs[(m4 * 4 + r) * SPV + dg * 8 + 4];
                vp[r][0] = v0.x; vp[r][1] = v0.y; vp[r][2] = v1.x; vp[r][3] = v1.y;
            }
            #pragma unroll
            for (int k = 0; k < 4; ++k) {
                float4 p4 = *(float4*)&ps[(rg + 32 * k) * SPP + m4 * 4];
                float pv[4] = {p4.x, p4.y, p4.z, p4.w};
                #pragma unroll
                for (int r = 0; r < 4; ++r) {
                    u64 pb = bcast2(pv[r]);
                    fma2(ctxp[k][0], pb, vp[r][0]);
                    fma2(ctxp[k][1], pb, vp[r][1]);
                    fma2(ctxp[k][2], pb, vp[r][2]);
                    fma2(ctxp[k][3], pb, vp[r][3]);
                }
            }
        }
    }

    #pragma unroll
    for (int k = 0; k < 4; ++k) {
        float f[8];
        #pragma unroll
        for (int jp = 0; jp < 4; ++jp) {
            float2 u = unpack2(ctxp[k][jp]);
            f[jp * 2] = u.x; f[jp * 2 + 1] = u.y;
        }
        size_t o = ((size_t)(b * N_ + r0 + rg + 32 * k)) * D_ + dg * 8;
        *(float4*)&g_ctx[o]     = make_float4(f[0], f[1], f[2], f[3]);
        *(float4*)&g_ctx[o + 4] = make_float4(f[4], f[5], f[6], f[7]);
    }
}

// ============================================================================
// Kernel 3: ctx2 = ctx@Wo+bo ; y = relu(x@Wl[0:64] + ctx2@Wl[64:128] + bl)
// grid (32, 16): 64 rows per block, 256 threads. Each thread: fixed d, 16 rows.
// ============================================================================
__global__ __launch_bounds__(256) void out_proj(
    const float* __restrict__ x,
    const float* __restrict__ Wo, const float* __restrict__ bo,
    const float* __restrict__ Wl, const float* __restrict__ bl,
    float* __restrict__ y)
{
    __shared__ float buf[64][64];   // ctx tile, then x tile
    __shared__ float c2s[64][64];
    __shared__ float Ws[64][64];

    const int tid = threadIdx.x;
    const int b = blockIdx.y, n0 = blockIdx.x * 64;
    const int d = tid & 63;

    for (int it = 0; it < 16; ++it) {
        int idx = tid + it * 256;
        int n = idx >> 6, dd = idx & 63;
        buf[n][dd] = g_ctx[((size_t)(b * N_ + n0 + n)) * D_ + dd];
        Ws[n][dd]  = Wo[idx];
    }
    __syncthreads();

    const float boD = bo[d];
    float c2loc[16];
    for (int it = 0; it < 16; ++it) {
        int n = (tid >> 6) + it * 4;
        float acc = boD;
        #pragma unroll
        for (int dd = 0; dd < 64; ++dd) acc += buf[n][dd] * Ws[dd][d];
        c2loc[it] = acc;
    }
    __syncthreads();   // all reads of buf/Ws done

    for (int it = 0; it < 16; ++it) {
        int n = (tid >> 6) + it * 4;
        c2s[n][d] = c2loc[it];
    }
    for (int it = 0; it < 16; ++it) {
        int idx = tid + it * 256;
        int n = idx >> 6, dd = idx & 63;
        buf[n][dd] = x[((size_t)(b * N_ + n0 + n)) * D_ + dd];
        Ws[n][dd]  = Wl[idx];          // Wl top half (rows 0..63)
    }
    __syncthreads();

    const float blD = bl[d];
    float yl[16];
    for (int it = 0; it < 16; ++it) {
        int n = (tid >> 6) + it * 4;
        float acc = blD;
        #pragma unroll
        for (int dd = 0; dd < 64; ++dd) acc += buf[n][dd] * Ws[dd][d];
        yl[it] = acc;
    }
    __syncthreads();

    for (int it = 0; it < 16; ++it) {
        int idx = tid + it * 256;
        Ws[idx >> 6][idx & 63] = Wl[64 * 64 + idx];   // Wl bottom half
    }
    __syncthreads();

    for (int it = 0; it < 16; ++it) {
        int n = (tid >> 6) + it * 4;
        float acc = yl[it];
        #pragma unroll
        for (int dd = 0; dd < 64; ++dd) acc += c2s[n][dd] * Ws[dd][d];
        y[((size_t)(b * N_ + n0 + n)) * D_ + d] = fmaxf(acc, 0.f);
    }
}

// ============================================================================
extern "C" void kernel_launch(void* const* d_in, const int* in_sizes, int n_in,
                              void* d_out, int out_size)
{
    const float* x   = (const float*)d_in[0];
    const int*   adj = (const int*)  d_in[1];
    const float* Wq  = (const float*)d_in[2];
    const float* bq  = (const float*)d_in[3];
    const float* Wk  = (const float*)d_in[4];
    const float* bk  = (const float*)d_in[5];
    const float* Wv  = (const float*)d_in[6];
    const float* bv  = (const float*)d_in[7];
    const float* Wo  = (const float*)d_in[8];
    const float* bo  = (const float*)d_in[9];
    const float* Wl  = (const float*)d_in[10];
    const float* bl  = (const float*)d_in[11];

    float* y    = (float*)d_out;                         // [B,N,D]
    float* attn = (float*)d_out + (size_t)B_ * N_ * D_;  // [B,N,N]

    cudaFuncSetAttribute(proj_qkv,
                         cudaFuncAttributeMaxDynamicSharedMemorySize,
                         PROJ_SMEM_BYTES);
    cudaFuncSetAttribute(attn_kernel,
                         cudaFuncAttributeMaxDynamicSharedMemorySize,
                         SMEM2_BYTES);

    proj_qkv<<<dim3(16, 16), 256, PROJ_SMEM_BYTES>>>(x, Wq, bq, Wk, bk, Wv, bv);
    attn_kernel<<<dim3(16, 16), 256, SMEM2_BYTES>>>(adj, attn);
    out_proj<<<dim3(32, 16), 256>>>(x, Wo, bo, Wl, bl, y);
}

// round 5
// speedup vs baseline: 1.3607x; 1.2468x over previous
#include <cuda_runtime.h>
#include <cuda_bf16.h>
#include <math.h>
#include <stdint.h>

#define B_ 16
#define N_ 2048
#define D_ 64
#define NEG_INF_ (-1e9f)

typedef unsigned int u32;

// ---------------------------- helpers ---------------------------------------
__device__ __forceinline__ u32 smem_u32(const void* p) {
    u32 a;
    asm("{ .reg .u64 t; cvta.to.shared.u64 t, %1; cvt.u32.u64 %0, t; }"
        : "=r"(a) : "l"(p));
    return a;
}
__device__ __forceinline__ void ldm4(u32* r, u32 a) {
    asm volatile("ldmatrix.sync.aligned.m8n8.x4.shared.b16 {%0,%1,%2,%3}, [%4];"
        : "=r"(r[0]), "=r"(r[1]), "=r"(r[2]), "=r"(r[3]) : "r"(a));
}
__device__ __forceinline__ void mma_bf16(float* c, const u32* a, u32 b0, u32 b1) {
    asm volatile("mma.sync.aligned.m16n8k16.row.col.f32.bf16.bf16.f32 "
        "{%0,%1,%2,%3}, {%4,%5,%6,%7}, {%8,%9}, {%0,%1,%2,%3};"
        : "+f"(c[0]), "+f"(c[1]), "+f"(c[2]), "+f"(c[3])
        : "r"(a[0]), "r"(a[1]), "r"(a[2]), "r"(a[3]), "r"(b0), "r"(b1));
}
// bf16 hi/lo split helpers
__device__ __forceinline__ u32 packbf2(float lo, float hi) {
    u32 r;
    asm("cvt.rn.bf16x2.f32 %0, %1, %2;" : "=r"(r) : "f"(hi), "f"(lo));
    return r;
}
__device__ __forceinline__ float bf_lo_f(u32 u) { return __uint_as_float(u << 16); }
__device__ __forceinline__ float bf_hi_f(u32 u) { return __uint_as_float(u & 0xffff0000u); }
__device__ __forceinline__ void split2(float a, float b, u32& h, u32& l) {
    h = packbf2(a, b);
    l = packbf2(a - bf_lo_f(h), b - bf_hi_f(h));
}

// ---------------- scratch (device globals; no allocation allowed) ----------
__device__ __nv_bfloat16 g_qh[(size_t)B_ * N_ * D_];
__device__ __nv_bfloat16 g_ql[(size_t)B_ * N_ * D_];
__device__ __nv_bfloat16 g_kh[(size_t)B_ * N_ * D_];
__device__ __nv_bfloat16 g_kl[(size_t)B_ * N_ * D_];
__device__ __nv_bfloat16 g_vTh[(size_t)B_ * D_ * N_];   // [B][D][N]
__device__ __nv_bfloat16 g_vTl[(size_t)B_ * D_ * N_];
__device__ float g_ctx[(size_t)B_ * N_ * D_];

// ============================================================================
// Kernel 1: projections -> bf16 hi/lo splits.
//   q,k: [B][N][64] row-major;  v: transposed [B][64][N]
// ============================================================================
#define PROJ_SMEM_BYTES ((64 * 132 + 64 * 64 + 64) * 4)

__global__ __launch_bounds__(256) void proj_qkv(
    const float* __restrict__ x,
    const float* __restrict__ Wq, const float* __restrict__ bq,
    const float* __restrict__ Wk, const float* __restrict__ bk,
    const float* __restrict__ Wv, const float* __restrict__ bv)
{
    extern __shared__ float psm[];
    float* xsT = psm;               // [64][132]  (d-major, n fast)
    float* Ws  = psm + 64 * 132;    // [64][64]
    float* bs  = Ws + 64 * 64;

    const int tid = threadIdx.x;
    const int b   = blockIdx.y;
    const int n0  = blockIdx.x * 128;

    for (int it = 0; it < 8; ++it) {
        int idx4 = tid + it * 256;
        int d4 = idx4 >> 7, n = idx4 & 127;
        float4 v = *(const float4*)&x[((size_t)(b * N_ + n0 + n)) * D_ + d4 * 4];
        xsT[(d4 * 4 + 0) * 132 + n] = v.x;
        xsT[(d4 * 4 + 1) * 132 + n] = v.y;
        xsT[(d4 * 4 + 2) * 132 + n] = v.z;
        xsT[(d4 * 4 + 3) * 132 + n] = v.w;
    }

    const int nlo  = (tid & 31) * 4;
    const int dblk = (tid >> 5) * 8;

    for (int mat = 0; mat < 3; ++mat) {
        const float* W  = (mat == 0) ? Wq : (mat == 1) ? Wk : Wv;
        const float* bb = (mat == 0) ? bq : (mat == 1) ? bk : bv;
        __syncthreads();
        for (int it = 0; it < 16; ++it) {
            int idx = tid + it * 256;
            Ws[idx] = W[idx];
        }
        if (tid < 64) bs[tid] = bb[tid];
        __syncthreads();

        float f[4][8];
        #pragma unroll
        for (int i = 0; i < 4; ++i)
            #pragma unroll
            for (int j = 0; j < 8; ++j) f[i][j] = bs[dblk + j];

        #pragma unroll 4
        for (int dd = 0; dd < 64; ++dd) {
            float4 a4 = *(float4*)&xsT[dd * 132 + nlo];
            float4 w0 = *(float4*)&Ws[dd * 64 + dblk];
            float4 w1 = *(float4*)&Ws[dd * 64 + dblk + 4];
            float av[4] = {a4.x, a4.y, a4.z, a4.w};
            float wv[8] = {w0.x, w0.y, w0.z, w0.w, w1.x, w1.y, w1.z, w1.w};
            #pragma unroll
            for (int i = 0; i < 4; ++i)
                #pragma unroll
                for (int j = 0; j < 8; ++j) f[i][j] += av[i] * wv[j];
        }

        if (mat < 2) {
            __nv_bfloat16* gh = (mat == 0) ? g_qh : g_kh;
            __nv_bfloat16* gl = (mat == 0) ? g_ql : g_kl;
            #pragma unroll
            for (int i = 0; i < 4; ++i) {
                uint4 hv, lv;
                split2(f[i][0], f[i][1], hv.x, lv.x);
                split2(f[i][2], f[i][3], hv.y, lv.y);
                split2(f[i][4], f[i][5], hv.z, lv.z);
                split2(f[i][6], f[i][7], hv.w, lv.w);
                size_t o = ((size_t)(b * N_ + n0 + nlo + i)) * D_ + dblk;
                *(uint4*)&gh[o] = hv;
                *(uint4*)&gl[o] = lv;
            }
        } else {
            #pragma unroll
            for (int j = 0; j < 8; ++j) {
                uint2 hv, lv;
                split2(f[0][j], f[1][j], hv.x, lv.x);
                split2(f[2][j], f[3][j], hv.y, lv.y);
                size_t o = ((size_t)(b * D_ + dblk + j)) * N_ + n0 + nlo;
                *(uint2*)&g_vTh[o] = hv;
                *(uint2*)&g_vTl[o] = lv;
            }
        }
    }
}

// ============================================================================
// Kernel 2: masked attention via mma.sync bf16x3 compensated.
// grid (16, 16) = (q-tile of 128 rows, batch). 256 threads = 8 warps.
// Warp w owns score/ctx rows w*16 .. w*16+15.
// Phase-1 tile stride 144B (16-aligned, conflict-free: 144 mod 128 = 16).
// Phase-2 tile stride 272B.
// ============================================================================
#define SM_STATS 0        // rowM[128] floats, rowL[128] floats
#define SM_QH    1024     // [128][144B]
#define SM_QL    (SM_QH + 18432)
#define SM_KH    (SM_QL + 18432)
#define SM_KL    (SM_KH + 18432)
#define SM_PH    1024     // [128][272B] phase-2 overlay
#define SM_PL    (SM_PH + 34816)
#define SM_VH    (SM_PL + 34816)   // [64][272B]
#define SM_VL    (SM_VH + 17408)
#define ATTN_SMEM (SM_VL + 17408)  // 105472 bytes

__global__ void __launch_bounds__(256) attn_kernel(
    const int* __restrict__ adj, float* __restrict__ attn)
{
    extern __shared__ char smem[];
    const u32 sb = smem_u32(smem);
    float* rowM = (float*)(smem + SM_STATS);
    float* rowL = (float*)(smem + SM_STATS + 512);

    const int tid = threadIdx.x;
    const int w   = tid >> 5;
    const int t   = tid & 31;
    const int b   = blockIdx.y;
    const int r0  = blockIdx.x * 128;

    // ---- load Q tiles (hi/lo), padded stride 144B ----
    {
        const size_t qbase = ((size_t)b * N_ + r0) * D_;
        for (int it = 0; it < 4; ++it) {
            int idx = tid + it * 256;               // 0..1023
            int r = idx >> 3, c = idx & 7;
            u32 off = (u32)(r * 144 + c * 16);
            *(uint4*)(smem + SM_QH + off) = *(const uint4*)&g_qh[qbase + (size_t)r * D_ + c * 8];
            *(uint4*)(smem + SM_QL + off) = *(const uint4*)&g_ql[qbase + (size_t)r * D_ + c * 8];
        }
    }

    const u32 aSel = (u32)((w * 16 + (t & 15)) * 144 + (t >> 4) * 16);
    const u32 bSel = (u32)((t & 15) * 144 + (t >> 4) * 16);

    float runM0 = -INFINITY, runL0 = 0.f;
    float runM1 = -INFINITY, runL1 = 0.f;

    const int rowA = t >> 2;                 // 0..7
    const int colq = (t & 3) * 2;            // 0,2,4,6
    const size_t growA = (size_t)(b * N_ + r0 + w * 16 + rowA) * N_;
    const size_t growB = growA + (size_t)8 * N_;

    // =================== Phase 1 ===================
    for (int mt = 0; mt < 16; ++mt) {
        const int m0 = mt * 128;
        __syncthreads();
        {
            const size_t kbase = ((size_t)b * N_ + m0) * D_;
            for (int it = 0; it < 4; ++it) {
                int idx = tid + it * 256;
                int r = idx >> 3, c = idx & 7;
                u32 off = (u32)(r * 144 + c * 16);
                *(uint4*)(smem + SM_KH + off) = *(const uint4*)&g_kh[kbase + (size_t)r * D_ + c * 8];
                *(uint4*)(smem + SM_KL + off) = *(const uint4*)&g_kl[kbase + (size_t)r * D_ + c * 8];
            }
        }
        __syncthreads();

        float acc[16][4];
        #pragma unroll
        for (int g = 0; g < 16; ++g)
            #pragma unroll
            for (int j = 0; j < 4; ++j) acc[g][j] = 0.f;

        #pragma unroll
        for (int ks = 0; ks < 4; ++ks) {
            const u32 k2 = ks * 32;
            u32 ah[4], al[4];
            ldm4(ah, sb + SM_QH + aSel + k2);
            ldm4(al, sb + SM_QL + aSel + k2);
            #pragma unroll
            for (int g = 0; g < 8; ++g) {
                u32 bh[4], bl[4];
                u32 boff = (u32)(g * 16 * 144) + bSel + k2;
                ldm4(bh, sb + SM_KH + boff);
                ldm4(bl, sb + SM_KL + boff);
                mma_bf16(acc[2 * g],     ah, bh[0], bh[2]);
                mma_bf16(acc[2 * g],     ah, bl[0], bl[2]);
                mma_bf16(acc[2 * g],     al, bh[0], bh[2]);
                mma_bf16(acc[2 * g + 1], ah, bh[1], bh[3]);
                mma_bf16(acc[2 * g + 1], ah, bl[1], bl[3]);
                mma_bf16(acc[2 * g + 1], al, bh[1], bh[3]);
            }
        }

        // mask + scale + scratch store
        #pragma unroll
        for (int g = 0; g < 16; ++g) {
            const int C = g * 8 + colq;
            const size_t adrA = growA + m0 + C;
            const size_t adrB = growB + m0 + C;
            int2 aA = *(const int2*)&adj[adrA];
            int2 aB = *(const int2*)&adj[adrB];
            acc[g][0] = (aA.x > 0) ? acc[g][0] * 0.125f : NEG_INF_;
            acc[g][1] = (aA.y > 0) ? acc[g][1] * 0.125f : NEG_INF_;
            acc[g][2] = (aB.x > 0) ? acc[g][2] * 0.125f : NEG_INF_;
            acc[g][3] = (aB.y > 0) ? acc[g][3] * 0.125f : NEG_INF_;
            *(float2*)&attn[adrA] = make_float2(acc[g][0], acc[g][1]);
            *(float2*)&attn[adrB] = make_float2(acc[g][2], acc[g][3]);
        }

        // online stats per row (quad shuffles)
        float tmA = -INFINITY, tmB = -INFINITY;
        #pragma unroll
        for (int g = 0; g < 16; ++g) {
            tmA = fmaxf(tmA, fmaxf(acc[g][0], acc[g][1]));
            tmB = fmaxf(tmB, fmaxf(acc[g][2], acc[g][3]));
        }
        tmA = fmaxf(tmA, __shfl_xor_sync(0xffffffffu, tmA, 1));
        tmA = fmaxf(tmA, __shfl_xor_sync(0xffffffffu, tmA, 2));
        tmB = fmaxf(tmB, __shfl_xor_sync(0xffffffffu, tmB, 1));
        tmB = fmaxf(tmB, __shfl_xor_sync(0xffffffffu, tmB, 2));
        float nmA = fmaxf(runM0, tmA);
        float nmB = fmaxf(runM1, tmB);
        float lA = 0.f, lB = 0.f;
        #pragma unroll
        for (int g = 0; g < 16; ++g) {
            lA += __expf(acc[g][0] - nmA) + __expf(acc[g][1] - nmA);
            lB += __expf(acc[g][2] - nmB) + __expf(acc[g][3] - nmB);
        }
        lA += __shfl_xor_sync(0xffffffffu, lA, 1);
        lA += __shfl_xor_sync(0xffffffffu, lA, 2);
        lB += __shfl_xor_sync(0xffffffffu, lB, 1);
        lB += __shfl_xor_sync(0xffffffffu, lB, 2);
        runL0 = runL0 * __expf(runM0 - nmA) + lA; runM0 = nmA;
        runL1 = runL1 * __expf(runM1 - nmB) + lB; runM1 = nmB;
    }

    if ((t & 3) == 0) {
        rowM[w * 16 + rowA]     = runM0;
        rowL[w * 16 + rowA]     = runL0;
        rowM[w * 16 + rowA + 8] = runM1;
        rowL[w * 16 + rowA + 8] = runL1;
    }
    __syncthreads();
    if (tid < 128) rowL[tid] = 1.f / rowL[tid];

    // =================== Phase 2 ===================
    float acc2[8][4];
    #pragma unroll
    for (int g = 0; g < 8; ++g)
        #pragma unroll
        for (int j = 0; j < 4; ++j) acc2[g][j] = 0.f;

    const u32 aSel2 = (u32)((w * 16 + (t & 15)) * 272 + (t >> 4) * 16);
    const u32 bSel2 = (u32)((t & 15) * 272 + (t >> 4) * 16);
    const size_t rbase = (size_t)(b * N_ + r0) * N_;

    for (int mt = 0; mt < 16; ++mt) {
        const int m0 = mt * 128;
        __syncthreads();   // prev mma done reading smem (also covers rowL invert)

        // V^T tiles (hi/lo): [64 d][128 key] padded stride 272B
        {
            const size_t vbase = (size_t)b * D_ * N_ + m0;
            for (int it = 0; it < 4; ++it) {
                int idx = tid + it * 256;            // 0..1023
                int d = idx >> 4, c8 = idx & 15;
                u32 off = (u32)(d * 272 + c8 * 16);
                *(uint4*)(smem + SM_VH + off) = *(const uint4*)&g_vTh[vbase + (size_t)d * N_ + c8 * 8];
                *(uint4*)(smem + SM_VL + off) = *(const uint4*)&g_vTl[vbase + (size_t)d * N_ + c8 * 8];
            }
        }

        // normalize scratch -> final attn + pack P hi/lo to smem
        for (int it = 0; it < 16; ++it) {
            int idx = tid + it * 256;                // 0..4095 float4 chunks
            int r = idx >> 5, c4 = idx & 31;
            const float M = rowM[r], iL = rowL[r];
            size_t adr = rbase + (size_t)r * N_ + m0 + c4 * 4;
            float4 s = *(const float4*)&attn[adr];
            float p0 = __expf(s.x - M) * iL;
            float p1 = __expf(s.y - M) * iL;
            float p2 = __expf(s.z - M) * iL;
            float p3 = __expf(s.w - M) * iL;
            *(float4*)&attn[adr] = make_float4(p0, p1, p2, p3);
            uint2 hv, lv;
            split2(p0, p1, hv.x, lv.x);
            split2(p2, p3, hv.y, lv.y);
            u32 off = (u32)(r * 272 + c4 * 8);
            *(uint2*)(smem + SM_PH + off) = hv;
            *(uint2*)(smem + SM_PL + off) = lv;
        }
        __syncthreads();

        // ctx += P @ V
        #pragma unroll
        for (int ks = 0; ks < 8; ++ks) {
            const u32 k2 = ks * 32;
            u32 ah[4], al[4];
            ldm4(ah, sb + SM_PH + aSel2 + k2);
            ldm4(al, sb + SM_PL + aSel2 + k2);
            #pragma unroll
            for (int g = 0; g < 4; ++g) {
                u32 bh[4], bl[4];
                u32 boff = (u32)(g * 16 * 272) + bSel2 + k2;
                ldm4(bh, sb + SM_VH + boff);
                ldm4(bl, sb + SM_VL + boff);
                mma_bf16(acc2[2 * g],     ah, bh[0], bh[2]);
                mma_bf16(acc2[2 * g],     ah, bl[0], bl[2]);
                mma_bf16(acc2[2 * g],     al, bh[0], bh[2]);
                mma_bf16(acc2[2 * g + 1], ah, bh[1], bh[3]);
                mma_bf16(acc2[2 * g + 1], ah, bl[1], bl[3]);
                mma_bf16(acc2[2 * g + 1], al, bh[1], bh[3]);
            }
        }
    }

    // write ctx
    {
        const size_t oA = (size_t)(b * N_ + r0 + w * 16 + rowA) * D_;
        const size_t oB = oA + 8 * D_;
        #pragma unroll
        for (int g = 0; g < 8; ++g) {
            const int C = g * 8 + colq;
            *(float2*)&g_ctx[oA + C] = make_float2(acc2[g][0], acc2[g][1]);
            *(float2*)&g_ctx[oB + C] = make_float2(acc2[g][2], acc2[g][3]);
        }
    }
}

// ============================================================================
// Kernel 3: ctx2 = ctx@Wo+bo ; y = relu(x@Wl[0:64] + ctx2@Wl[64:128] + bl)
// ============================================================================
__global__ __launch_bounds__(256) void out_proj(
    const float* __restrict__ x,
    const float* __restrict__ Wo, const float* __restrict__ bo,
    const float* __restrict__ Wl, const float* __restrict__ bl,
    float* __restrict__ y)
{
    __shared__ float buf[64][64];
    __shared__ float c2s[64][64];
    __shared__ float Ws[64][64];

    const int tid = threadIdx.x;
    const int b = blockIdx.y, n0 = blockIdx.x * 64;
    const int d = tid & 63;

    for (int it = 0; it < 16; ++it) {
        int idx = tid + it * 256;
        int n = idx >> 6, dd = idx & 63;
        buf[n][dd] = g_ctx[((size_t)(b * N_ + n0 + n)) * D_ + dd];
        Ws[n][dd]  = Wo[idx];
    }
    __syncthreads();

    const float boD = bo[d];
    float c2loc[16];
    for (int it = 0; it < 16; ++it) {
        int n = (tid >> 6) + it * 4;
        float acc = boD;
        #pragma unroll
        for (int dd = 0; dd < 64; ++dd) acc += buf[n][dd] * Ws[dd][d];
        c2loc[it] = acc;
    }
    __syncthreads();

    for (int it = 0; it < 16; ++it) {
        int n = (tid >> 6) + it * 4;
        c2s[n][d] = c2loc[it];
    }
    for (int it = 0; it < 16; ++it) {
        int idx = tid + it * 256;
        int n = idx >> 6, dd = idx & 63;
        buf[n][dd] = x[((size_t)(b * N_ + n0 + n)) * D_ + dd];
        Ws[n][dd]  = Wl[idx];
    }
    __syncthreads();

    const float blD = bl[d];
    float yl[16];
    for (int it = 0; it < 16; ++it) {
        int n = (tid >> 6) + it * 4;
        float acc = blD;
        #pragma unroll
        for (int dd = 0; dd < 64; ++dd) acc += buf[n][dd] * Ws[dd][d];
        yl[it] = acc;
    }
    __syncthreads();

    for (int it = 0; it < 16; ++it) {
        int idx = tid + it * 256;
        Ws[idx >> 6][idx & 63] = Wl[64 * 64 + idx];
    }
    __syncthreads();

    for (int it = 0; it < 16; ++it) {
        int n = (tid >> 6) + it * 4;
        float acc = yl[it];
        #pragma unroll
        for (int dd = 0; dd < 64; ++dd) acc += c2s[n][dd] * Ws[dd][d];
        y[((size_t)(b * N_ + n0 + n)) * D_ + d] = fmaxf(acc, 0.f);
    }
}

// ============================================================================
extern "C" void kernel_launch(void* const* d_in, const int* in_sizes, int n_in,
                              void* d_out, int out_size)
{
    const float* x   = (const float*)d_in[0];
    const int*   adj = (const int*)  d_in[1];
    const float* Wq  = (const float*)d_in[2];
    const float* bq  = (const float*)d_in[3];
    const float* Wk  = (const float*)d_in[4];
    const float* bk  = (const float*)d_in[5];
    const float* Wv  = (const float*)d_in[6];
    const float* bv  = (const float*)d_in[7];
    const float* Wo  = (const float*)d_in[8];
    const float* bo  = (const float*)d_in[9];
    const float* Wl  = (const float*)d_in[10];
    const float* bl  = (const float*)d_in[11];

    float* y    = (float*)d_out;                         // [B,N,D]
    float* attn = (float*)d_out + (size_t)B_ * N_ * D_;  // [B,N,N]

    cudaFuncSetAttribute(proj_qkv,
                         cudaFuncAttributeMaxDynamicSharedMemorySize,
                         PROJ_SMEM_BYTES);
    cudaFuncSetAttribute(attn_kernel,
                         cudaFuncAttributeMaxDynamicSharedMemorySize,
                         ATTN_SMEM);

    proj_qkv<<<dim3(16, 16), 256, PROJ_SMEM_BYTES>>>(x, Wq, bq, Wk, bk, Wv, bv);
    attn_kernel<<<dim3(16, 16), 256, ATTN_SMEM>>>(adj, attn);
    out_proj<<<dim3(32, 16), 256>>>(x, Wo, bo, Wl, bl, y);
}

// round 6
// speedup vs baseline: 2.3094x; 1.6972x over previous
#include <cuda_runtime.h>
#include <cuda_fp16.h>
#include <math.h>
#include <stdint.h>

#define B_ 16
#define N_ 2048
#define D_ 64
#define NEG_INF_ (-1e9f)

typedef unsigned int u32;

// ---------------------------- helpers ---------------------------------------
__device__ __forceinline__ u32 smem_u32(const void* p) {
    u32 a;
    asm("{ .reg .u64 t; cvta.to.shared.u64 t, %1; cvt.u32.u64 %0, t; }"
        : "=r"(a) : "l"(p));
    return a;
}
__device__ __forceinline__ void ldm4(u32* r, u32 a) {
    asm volatile("ldmatrix.sync.aligned.m8n8.x4.shared.b16 {%0,%1,%2,%3}, [%4];"
        : "=r"(r[0]), "=r"(r[1]), "=r"(r[2]), "=r"(r[3]) : "r"(a));
}
__device__ __forceinline__ void mma_f16(float* c, const u32* a, u32 b0, u32 b1) {
    asm volatile("mma.sync.aligned.m16n8k16.row.col.f32.f16.f16.f32 "
        "{%0,%1,%2,%3}, {%4,%5,%6,%7}, {%8,%9}, {%0,%1,%2,%3};"
        : "+f"(c[0]), "+f"(c[1]), "+f"(c[2]), "+f"(c[3])
        : "r"(a[0]), "r"(a[1]), "r"(a[2]), "r"(a[3]), "r"(b0), "r"(b1));
}
__device__ __forceinline__ u32 packh2(float lo, float hi) {
    __half2 h = __floats2half2_rn(lo, hi);   // .x = lo (low half)
    return *(u32*)&h;
}

// ---------------- scratch (device globals; no allocation allowed) ----------
__device__ __half g_q[(size_t)B_ * N_ * D_];    // pre-scaled by 1/8
__device__ __half g_k[(size_t)B_ * N_ * D_];
__device__ __half g_v[(size_t)B_ * D_ * N_];    // transposed [B][64][N]
__device__ float  g_ctx[(size_t)B_ * N_ * D_];

// ============================================================================
// Kernel 1: projections -> fp16. q scaled by 0.125; v stored transposed.
// ============================================================================
#define PROJ_SMEM_BYTES ((64 * 132 + 64 * 64 + 64) * 4)

__global__ __launch_bounds__(256) void proj_qkv(
    const float* __restrict__ x,
    const float* __restrict__ Wq, const float* __restrict__ bq,
    const float* __restrict__ Wk, const float* __restrict__ bk,
    const float* __restrict__ Wv, const float* __restrict__ bv)
{
    extern __shared__ float psm[];
    float* xsT = psm;               // [64][132]
    float* Ws  = psm + 64 * 132;    // [64][64]
    float* bs  = Ws + 64 * 64;

    const int tid = threadIdx.x;
    const int b   = blockIdx.y;
    const int n0  = blockIdx.x * 128;

    for (int it = 0; it < 8; ++it) {
        int idx4 = tid + it * 256;
        int d4 = idx4 >> 7, n = idx4 & 127;
        float4 v = *(const float4*)&x[((size_t)(b * N_ + n0 + n)) * D_ + d4 * 4];
        xsT[(d4 * 4 + 0) * 132 + n] = v.x;
        xsT[(d4 * 4 + 1) * 132 + n] = v.y;
        xsT[(d4 * 4 + 2) * 132 + n] = v.z;
        xsT[(d4 * 4 + 3) * 132 + n] = v.w;
    }

    const int nlo  = (tid & 31) * 4;
    const int dblk = (tid >> 5) * 8;

    for (int mat = 0; mat < 3; ++mat) {
        const float* W  = (mat == 0) ? Wq : (mat == 1) ? Wk : Wv;
        const float* bb = (mat == 0) ? bq : (mat == 1) ? bk : bv;
        __syncthreads();
        for (int it = 0; it < 16; ++it) {
            int idx = tid + it * 256;
            Ws[idx] = W[idx];
        }
        if (tid < 64) bs[tid] = bb[tid];
        __syncthreads();

        float f[4][8];
        #pragma unroll
        for (int i = 0; i < 4; ++i)
            #pragma unroll
            for (int j = 0; j < 8; ++j) f[i][j] = bs[dblk + j];

        #pragma unroll 4
        for (int dd = 0; dd < 64; ++dd) {
            float4 a4 = *(float4*)&xsT[dd * 132 + nlo];
            float4 w0 = *(float4*)&Ws[dd * 64 + dblk];
            float4 w1 = *(float4*)&Ws[dd * 64 + dblk + 4];
            float av[4] = {a4.x, a4.y, a4.z, a4.w};
            float wv[8] = {w0.x, w0.y, w0.z, w0.w, w1.x, w1.y, w1.z, w1.w};
            #pragma unroll
            for (int i = 0; i < 4; ++i)
                #pragma unroll
                for (int j = 0; j < 8; ++j) f[i][j] += av[i] * wv[j];
        }

        if (mat == 0) {
            #pragma unroll
            for (int i = 0; i < 4; ++i)
                #pragma unroll
                for (int j = 0; j < 8; ++j) f[i][j] *= 0.125f;
        }

        if (mat < 2) {
            __half* g = (mat == 0) ? g_q : g_k;
            #pragma unroll
            for (int i = 0; i < 4; ++i) {
                uint4 hv;
                hv.x = packh2(f[i][0], f[i][1]);
                hv.y = packh2(f[i][2], f[i][3]);
                hv.z = packh2(f[i][4], f[i][5]);
                hv.w = packh2(f[i][6], f[i][7]);
                *(uint4*)&g[((size_t)(b * N_ + n0 + nlo + i)) * D_ + dblk] = hv;
            }
        } else {
            #pragma unroll
            for (int j = 0; j < 8; ++j) {
                uint2 hv;
                hv.x = packh2(f[0][j], f[1][j]);
                hv.y = packh2(f[2][j], f[3][j]);
                *(uint2*)&g_v[((size_t)(b * D_ + dblk + j)) * N_ + n0 + nlo] = hv;
            }
        }
    }
}

// ============================================================================
// Kernel 2: masked attention, 2-pass recompute, fp16 mma.sync, no scratch.
// grid (16, 16) = (q-tile of 128 rows, batch). 256 threads = 8 warps.
// Phase 1: S = QK^T (MMA), mask from adj (stashed as bits in smem), row
//          max/sum only — no global stores.
// Phase 2: recompute S, normalize in registers, write final attn once,
//          PV GEMM with A-fragments taken directly from S accumulators.
// ============================================================================
#define SM_STATS 0                   // rowM[128], rowL[128]
#define SM_MASK  1024                // 16 tiles * 256 threads * 8B = 32768
#define SM_K     (SM_MASK + 32768)   // [128][144B] = 18432
#define SM_V     (SM_K + 18432)      // phase1: Q overlay [128][144]; phase2: V [64][272]
#define ATTN_SMEM (SM_V + 18432)     // 70656 bytes

__global__ void __launch_bounds__(256, 2) attn_kernel(
    const int* __restrict__ adj, float* __restrict__ attn)
{
    extern __shared__ char smem[];
    const u32 sb = smem_u32(smem);
    float* rowM = (float*)(smem);
    float* rowL = (float*)(smem + 512);
    uint2* maskS = (uint2*)(smem + SM_MASK);

    const int tid = threadIdx.x;
    const int w   = tid >> 5;
    const int t   = tid & 31;
    const int b   = blockIdx.y;
    const int r0  = blockIdx.x * 128;

    const int rowA = t >> 2;            // 0..7
    const int colq = (t & 3) * 2;       // 0,2,4,6
    const u32 aSel  = (u32)((w * 16 + (t & 15)) * 144 + (t >> 4) * 16);
    const u32 bSel  = (u32)((t & 15) * 144 + (t >> 4) * 16);
    const u32 bSel2 = (u32)((t & 15) * 272 + (t >> 4) * 16);

    // ---- load Q tile (into V slot), grab A-fragments into registers ----
    {
        const size_t qbase = ((size_t)b * N_ + r0) * D_;
        for (int it = 0; it < 4; ++it) {
            int idx = tid + it * 256;          // 0..1023
            int r = idx >> 3, c = idx & 7;
            *(uint4*)(smem + SM_V + r * 144 + c * 16) =
                *(const uint4*)&g_q[qbase + (size_t)r * D_ + c * 8];
        }
    }
    __syncthreads();
    u32 qa[4][4];
    #pragma unroll
    for (int ks = 0; ks < 4; ++ks) ldm4(qa[ks], sb + SM_V + aSel + ks * 32);

    float runM0 = -INFINITY, runL0 = 0.f;
    float runM1 = -INFINITY, runL1 = 0.f;
    const size_t growA = (size_t)(b * N_ + r0 + w * 16 + rowA) * N_;
    const size_t growB = growA + (size_t)8 * N_;

    // =================== Phase 1: stats only ===================
    for (int mt = 0; mt < 16; ++mt) {
        const int m0 = mt * 128;
        __syncthreads();
        {
            const size_t kbase = ((size_t)b * N_ + m0) * D_;
            for (int it = 0; it < 4; ++it) {
                int idx = tid + it * 256;
                int r = idx >> 3, c = idx & 7;
                *(uint4*)(smem + SM_K + r * 144 + c * 16) =
                    *(const uint4*)&g_k[kbase + (size_t)r * D_ + c * 8];
            }
        }
        __syncthreads();

        float acc[16][4];
        #pragma unroll
        for (int g = 0; g < 16; ++g)
            #pragma unroll
            for (int j = 0; j < 4; ++j) acc[g][j] = 0.f;

        #pragma unroll
        for (int ks = 0; ks < 4; ++ks) {
            const u32 k2 = ks * 32;
            #pragma unroll
            for (int g = 0; g < 8; ++g) {
                u32 bh[4];
                ldm4(bh, sb + SM_K + (u32)(g * 2304) + bSel + k2);
                mma_f16(acc[2 * g],     qa[ks], bh[0], bh[2]);
                mma_f16(acc[2 * g + 1], qa[ks], bh[1], bh[3]);
            }
        }

        // mask from adj, stash bits, masked stats
        u32 mlo = 0, mhi = 0;
        float tmA = -INFINITY, tmB = -INFINITY;
        #pragma unroll
        for (int g = 0; g < 16; ++g) {
            const int C = g * 8 + colq;
            int2 aA = *(const int2*)&adj[growA + m0 + C];
            int2 aB = *(const int2*)&adj[growB + m0 + C];
            float s0 = (aA.x > 0) ? acc[g][0] : NEG_INF_;
            float s1 = (aA.y > 0) ? acc[g][1] : NEG_INF_;
            float s2 = (aB.x > 0) ? acc[g][2] : NEG_INF_;
            float s3 = (aB.y > 0) ? acc[g][3] : NEG_INF_;
            u32 bits = (u32)(aA.x > 0) | ((u32)(aA.y > 0) << 1)
                     | ((u32)(aB.x > 0) << 2) | ((u32)(aB.y > 0) << 3);
            if (g < 8) mlo |= bits << (g * 4); else mhi |= bits << ((g - 8) * 4);
            acc[g][0] = s0; acc[g][1] = s1; acc[g][2] = s2; acc[g][3] = s3;
            tmA = fmaxf(tmA, fmaxf(s0, s1));
            tmB = fmaxf(tmB, fmaxf(s2, s3));
        }
        maskS[mt * 256 + tid] = make_uint2(mlo, mhi);

        tmA = fmaxf(tmA, __shfl_xor_sync(0xffffffffu, tmA, 1));
        tmA = fmaxf(tmA, __shfl_xor_sync(0xffffffffu, tmA, 2));
        tmB = fmaxf(tmB, __shfl_xor_sync(0xffffffffu, tmB, 1));
        tmB = fmaxf(tmB, __shfl_xor_sync(0xffffffffu, tmB, 2));
        float nmA = fmaxf(runM0, tmA);
        float nmB = fmaxf(runM1, tmB);
        float lA = 0.f, lB = 0.f;
        #pragma unroll
        for (int g = 0; g < 16; ++g) {
            lA += __expf(acc[g][0] - nmA) + __expf(acc[g][1] - nmA);
            lB += __expf(acc[g][2] - nmB) + __expf(acc[g][3] - nmB);
        }
        lA += __shfl_xor_sync(0xffffffffu, lA, 1);
        lA += __shfl_xor_sync(0xffffffffu, lA, 2);
        lB += __shfl_xor_sync(0xffffffffu, lB, 1);
        lB += __shfl_xor_sync(0xffffffffu, lB, 2);
        runL0 = runL0 * __expf(runM0 - nmA) + lA; runM0 = nmA;
        runL1 = runL1 * __expf(runM1 - nmB) + lB; runM1 = nmB;
    }

    if ((t & 3) == 0) {
        rowM[w * 16 + rowA]     = runM0;
        rowL[w * 16 + rowA]     = runL0;
        rowM[w * 16 + rowA + 8] = runM1;
        rowL[w * 16 + rowA + 8] = runL1;
    }
    __syncthreads();
    if (tid < 128) rowL[tid] = 1.f / rowL[tid];
    __syncthreads();
    const float M0 = rowM[w * 16 + rowA],     iL0 = rowL[w * 16 + rowA];
    const float M1 = rowM[w * 16 + rowA + 8], iL1 = rowL[w * 16 + rowA + 8];

    // =================== Phase 2: recompute + final write + PV ==============
    float acc2[8][4];
    #pragma unroll
    for (int g = 0; g < 8; ++g)
        #pragma unroll
        for (int j = 0; j < 4; ++j) acc2[g][j] = 0.f;

    for (int mt = 0; mt < 16; ++mt) {
        const int m0 = mt * 128;
        __syncthreads();   // previous tile's MMAs done reading smem
        {
            const size_t kbase = ((size_t)b * N_ + m0) * D_;
            const size_t vbase = (size_t)b * D_ * N_ + m0;
            for (int it = 0; it < 4; ++it) {
                int idx = tid + it * 256;
                int r = idx >> 3, c = idx & 7;
                *(uint4*)(smem + SM_K + r * 144 + c * 16) =
                    *(const uint4*)&g_k[kbase + (size_t)r * D_ + c * 8];
                int d = idx >> 4, c8 = idx & 15;
                *(uint4*)(smem + SM_V + d * 272 + c8 * 16) =
                    *(const uint4*)&g_v[vbase + (size_t)d * N_ + c8 * 8];
            }
        }
        __syncthreads();

        float acc[16][4];
        #pragma unroll
        for (int g = 0; g < 16; ++g)
            #pragma unroll
            for (int j = 0; j < 4; ++j) acc[g][j] = 0.f;

        #pragma unroll
        for (int ks = 0; ks < 4; ++ks) {
            const u32 k2 = ks * 32;
            #pragma unroll
            for (int g = 0; g < 8; ++g) {
                u32 bh[4];
                ldm4(bh, sb + SM_K + (u32)(g * 2304) + bSel + k2);
                mma_f16(acc[2 * g],     qa[ks], bh[0], bh[2]);
                mma_f16(acc[2 * g + 1], qa[ks], bh[1], bh[3]);
            }
        }

        // normalize in regs, write final attn, keep p in acc for PV frags
        const uint2 mk = maskS[mt * 256 + tid];
        #pragma unroll
        for (int g = 0; g < 16; ++g) {
            u32 bits = ((g < 8) ? mk.x : mk.y) >> ((g & 7) * 4);
            float s0 = (bits & 1u) ? acc[g][0] : NEG_INF_;
            float s1 = (bits & 2u) ? acc[g][1] : NEG_INF_;
            float s2 = (bits & 4u) ? acc[g][2] : NEG_INF_;
            float s3 = (bits & 8u) ? acc[g][3] : NEG_INF_;
            float p0 = __expf(s0 - M0) * iL0;
            float p1 = __expf(s1 - M0) * iL0;
            float p2 = __expf(s2 - M1) * iL1;
            float p3 = __expf(s3 - M1) * iL1;
            const int C = g * 8 + colq;
            *(float2*)&attn[growA + m0 + C] = make_float2(p0, p1);
            *(float2*)&attn[growB + m0 + C] = make_float2(p2, p3);
            acc[g][0] = p0; acc[g][1] = p1; acc[g][2] = p2; acc[g][3] = p3;
        }

        // ctx += P @ V, A-fragments straight from accumulators
        #pragma unroll
        for (int kk = 0; kk < 8; ++kk) {
            u32 af[4];
            af[0] = packh2(acc[2 * kk][0],     acc[2 * kk][1]);
            af[1] = packh2(acc[2 * kk][2],     acc[2 * kk][3]);
            af[2] = packh2(acc[2 * kk + 1][0], acc[2 * kk + 1][1]);
            af[3] = packh2(acc[2 * kk + 1][2], acc[2 * kk + 1][3]);
            const u32 k2 = kk * 32;
            #pragma unroll
            for (int gd = 0; gd < 4; ++gd) {
                u32 bh[4];
                ldm4(bh, sb + SM_V + (u32)(gd * 4352) + bSel2 + k2);
                mma_f16(acc2[2 * gd],     af, bh[0], bh[2]);
                mma_f16(acc2[2 * gd + 1], af, bh[1], bh[3]);
            }
        }
    }

    // write ctx
    {
        const size_t oA = (size_t)(b * N_ + r0 + w * 16 + rowA) * D_;
        const size_t oB = oA + 8 * D_;
        #pragma unroll
        for (int g = 0; g < 8; ++g) {
            const int C = g * 8 + colq;
            *(float2*)&g_ctx[oA + C] = make_float2(acc2[g][0], acc2[g][1]);
            *(float2*)&g_ctx[oB + C] = make_float2(acc2[g][2], acc2[g][3]);
        }
    }
}

// ============================================================================
// Kernel 3: ctx2 = ctx@Wo+bo ; y = relu(x@Wl[0:64] + ctx2@Wl[64:128] + bl)
// ============================================================================
__global__ __launch_bounds__(256) void out_proj(
    const float* __restrict__ x,
    const float* __restrict__ Wo, const float* __restrict__ bo,
    const float* __restrict__ Wl, const float* __restrict__ bl,
    float* __restrict__ y)
{
    __shared__ float buf[64][64];
    __shared__ float c2s[64][64];
    __shared__ float Ws[64][64];

    const int tid = threadIdx.x;
    const int b = blockIdx.y, n0 = blockIdx.x * 64;
    const int d = tid & 63;

    for (int it = 0; it < 16; ++it) {
        int idx = tid + it * 256;
        int n = idx >> 6, dd = idx & 63;
        buf[n][dd] = g_ctx[((size_t)(b * N_ + n0 + n)) * D_ + dd];
        Ws[n][dd]  = Wo[idx];
    }
    __syncthreads();

    const float boD = bo[d];
    float c2loc[16];
    for (int it = 0; it < 16; ++it) {
        int n = (tid >> 6) + it * 4;
        float acc = boD;
        #pragma unroll
        for (int dd = 0; dd < 64; ++dd) acc += buf[n][dd] * Ws[dd][d];
        c2loc[it] = acc;
    }
    __syncthreads();

    for (int it = 0; it < 16; ++it) {
        int n = (tid >> 6) + it * 4;
        c2s[n][d] = c2loc[it];
    }
    for (int it = 0; it < 16; ++it) {
        int idx = tid + it * 256;
        int n = idx >> 6, dd = idx & 63;
        buf[n][dd] = x[((size_t)(b * N_ + n0 + n)) * D_ + dd];
        Ws[n][dd]  = Wl[idx];
    }
    __syncthreads();

    const float blD = bl[d];
    float yl[16];
    for (int it = 0; it < 16; ++it) {
        int n = (tid >> 6) + it * 4;
        float acc = blD;
        #pragma unroll
        for (int dd = 0; dd < 64; ++dd) acc += buf[n][dd] * Ws[dd][d];
        yl[it] = acc;
    }
    __syncthreads();

    for (int it = 0; it < 16; ++it) {
        int idx = tid + it * 256;
        Ws[idx >> 6][idx & 63] = Wl[64 * 64 + idx];
    }
    __syncthreads();

    for (int it = 0; it < 16; ++it) {
        int n = (tid >> 6) + it * 4;
        float acc = yl[it];
        #pragma unroll
        for (int dd = 0; dd < 64; ++dd) acc += c2s[n][dd] * Ws[dd][d];
        y[((size_t)(b * N_ + n0 + n)) * D_ + d] = fmaxf(acc, 0.f);
    }
}

// ============================================================================
extern "C" void kernel_launch(void* const* d_in, const int* in_sizes, int n_in,
                              void* d_out, int out_size)
{
    const float* x   = (const float*)d_in[0];
    const int*   adj = (const int*)  d_in[1];
    const float* Wq  = (const float*)d_in[2];
    const float* bq  = (const float*)d_in[3];
    const float* Wk  = (const float*)d_in[4];
    const float* bk  = (const float*)d_in[5];
    const float* Wv  = (const float*)d_in[6];
    const float* bv  = (const float*)d_in[7];
    const float* Wo  = (const float*)d_in[8];
    const float* bo  = (const float*)d_in[9];
    const float* Wl  = (const float*)d_in[10];
    const float* bl  = (const float*)d_in[11];

    float* y    = (float*)d_out;                         // [B,N,D]
    float* attn = (float*)d_out + (size_t)B_ * N_ * D_;  // [B,N,N]

    cudaFuncSetAttribute(proj_qkv,
                         cudaFuncAttributeMaxDynamicSharedMemorySize,
                         PROJ_SMEM_BYTES);
    cudaFuncSetAttribute(attn_kernel,
                         cudaFuncAttributeMaxDynamicSharedMemorySize,
                         ATTN_SMEM);

    proj_qkv<<<dim3(16, 16), 256, PROJ_SMEM_BYTES>>>(x, Wq, bq, Wk, bk, Wv, bv);
    attn_kernel<<<dim3(16, 16), 256, ATTN_SMEM>>>(adj, attn);
    out_proj<<<dim3(32, 16), 256>>>(x, Wo, bo, Wl, bl, y);
}